// round 3
// baseline (speedup 1.0000x reference)
#include <cuda_runtime.h>

// NeRF fine sampling + merge. One warp per ray.
// SC=64 sorted coarse dists, 63 weights, SF=128 fine samples, out 192 sorted.
#define SC   64
#define SF   128
#define NOUT 192
#define WPB  8
#define FULL 0xffffffffu

__device__ __forceinline__ void ce(float& x, float& y, bool asc) {
    float lo = fminf(x, y), hi = fmaxf(x, y);
    x = asc ? lo : hi;
    y = asc ? hi : lo;
}

__global__ __launch_bounds__(32 * WPB, 7)
void fine_sample_kernel(const float* __restrict__ dists,
                        const float* __restrict__ weights,
                        const float* __restrict__ rands,
                        float* __restrict__ out, int B)
{
    __shared__ float  cdfs_s[WPB][SC];   // scalar cdf for search probes
    __shared__ float4 quad_s[WPB][SC];   // (cdf[i], cdf[i+1], d[i], d[i+1])
    __shared__ int    pref_s[WPB][SC];   // prefix table for dist placement
    __shared__ float  out_s[WPB][NOUT];

    const int wid  = threadIdx.x >> 5;
    const int lane = threadIdx.x & 31;
    const int ray  = blockIdx.x * WPB + wid;
    if (ray >= B) return;

    float*  cdfs = cdfs_s[wid];
    float4* quad = quad_s[wid];
    int*    pref = pref_s[wid];
    float*  obf  = out_s[wid];

    // prefix table default: "no sample has bin >= j" -> 128
    pref[lane]      = 128;
    pref[lane + 32] = 128;

    // ---- load coarse dists ----
    const float* dptr = dists + (size_t)ray * SC;
    float dA = dptr[lane];
    float dB = dptr[32 + lane];

    // ---- weights -> normalized CDF ----
    const float* wptr = weights + (size_t)ray * (SC - 1);
    float w0 = wptr[lane] + 0.01f;
    float w1 = (lane < 31) ? (wptr[32 + lane] + 0.01f) : 0.0f;

    float a = w0;
    #pragma unroll
    for (int off = 1; off < 32; off <<= 1) {
        float t = __shfl_up_sync(FULL, a, off);
        if (lane >= off) a += t;
    }
    float total0 = __shfl_sync(FULL, a, 31);
    float b = w1;
    #pragma unroll
    for (int off = 1; off < 32; off <<= 1) {
        float t = __shfl_up_sync(FULL, b, off);
        if (lane >= off) b += t;
    }
    float total = total0 + __shfl_sync(FULL, b, 30);
    float inv = 1.0f / total;

    float v1 = a * inv;              // cdf[lane+1]
    float v2 = (total0 + b) * inv;   // cdf[lane+33] (lane 31 == cdf[63] dup)

    if (lane == 0) cdfs[0] = 0.0f;
    cdfs[lane + 1] = v1;
    if (lane < 31) cdfs[lane + 33] = v2;

    float c32v = __shfl_sync(FULL, v1, 31);
    float cl = __shfl_up_sync(FULL, v1, 1); if (lane == 0) cl = 0.0f;   // cdf[lane]
    float ch = __shfl_up_sync(FULL, v2, 1); if (lane == 0) ch = c32v;   // cdf[lane+32]

    // d neighbors
    float dB0 = __shfl_sync(FULL, dB, 0);
    float dA1 = __shfl_down_sync(FULL, dA, 1); if (lane == 31) dA1 = dB0; // d[lane+1]
    float dB1 = __shfl_down_sync(FULL, dB, 1);                            // d[lane+33], lane31 -> dB (self)

    quad[lane]      = make_float4(cl, v1, dA, dA1);
    quad[lane + 32] = make_float4(ch, v2, dB, dB1);

    // register-resident top search levels
    float c16 = __shfl_sync(FULL, v1, 15);
    float c8  = __shfl_sync(FULL, v1, 7);
    float c24 = __shfl_sync(FULL, v1, 23);
    float c48 = __shfl_sync(FULL, v2, 15);
    float c40 = __shfl_sync(FULL, v2, 7);
    float c56 = __shfl_sync(FULL, v2, 23);
    __syncwarp();

    // ---- 4 samples per lane, element index i = lane*4 + m ----
    const float4* u4p = (const float4*)(rands + (size_t)ray * SF);
    float4 uu = u4p[lane];
    float uarr[4] = {uu.x, uu.y, uu.z, uu.w};
    float k[4];

    #pragma unroll
    for (int m = 0; m < 4; m++) {
        float u = uarr[m];
        int idx = (c32v <= u) ? 32 : 0;
        float p2 = idx ? c48 : c16;
        if (p2 <= u) idx += 16;
        float p3 = (idx & 32) ? ((idx & 16) ? c56 : c40)
                              : ((idx & 16) ? c24 : c8);
        if (p3 <= u) idx += 8;
        if (cdfs[idx + 4] <= u) idx += 4;
        if (cdfs[idx + 2] <= u) idx += 2;
        if (cdfs[idx + 1] <= u) idx += 1;
        float4 q = quad[idx];
        float den = q.y - q.x;
        den = (den < 1e-5f) ? 1.0f : den;
        float t = (u - q.x) / den;
        float s = fmaf(t, q.w - q.z, q.z);
        s = fminf(s, q.w);   // bin-monotone keys
        k[m] = __uint_as_float((__float_as_uint(s) & ~63u) | (unsigned)idx);
    }

    // ---- bitonic sort of 128 keys, blocked mapping i = lane*4+m ----
    ce(k[0], k[1], true);  ce(k[2], k[3], false);       // k=2
    {                                                    // k=4
        bool a4 = (lane & 1) == 0;
        ce(k[0], k[2], a4); ce(k[1], k[3], a4);
        ce(k[0], k[1], a4); ce(k[2], k[3], a4);
    }
    #pragma unroll
    for (int kk = 8; kk <= SF; kk <<= 1) {
        bool asc = (lane & (kk >> 2)) == 0;
        #pragma unroll
        for (int j = kk >> 1; j >= 4; j >>= 1) {
            int L = j >> 2;                  // lane distance
            bool domin = (((lane & L) == 0) == asc);
            #pragma unroll
            for (int m = 0; m < 4; m++) {
                float p = __shfl_xor_sync(FULL, k[m], L);
                k[m] = domin ? fminf(k[m], p) : fmaxf(k[m], p);
            }
        }
        ce(k[0], k[2], asc); ce(k[1], k[3], asc);
        ce(k[0], k[1], asc); ce(k[2], k[3], asc);
    }

    // ---- bins are non-decreasing with rank: boundary scatter builds prefix ----
    int bb[4];
    #pragma unroll
    for (int m = 0; m < 4; m++) bb[m] = (int)(__float_as_uint(k[m]) & 63u);
    int pb = __shfl_up_sync(FULL, bb[3], 1);
    if (lane == 0) pb = -1;
    {
        int base = lane * 4;
        for (int j = pb + 1;    j <= bb[0]; j++) pref[j] = base;
        for (int j = bb[0] + 1; j <= bb[1]; j++) pref[j] = base + 1;
        for (int j = bb[1] + 1; j <= bb[2]; j++) pref[j] = base + 2;
        for (int j = bb[2] + 1; j <= bb[3]; j++) pref[j] = base + 3;
    }

    // ---- scatter samples: pos = rank + bin + 1 ----
    #pragma unroll
    for (int m = 0; m < 4; m++) {
        unsigned bits = __float_as_uint(k[m]);
        obf[lane * 4 + m + bb[m] + 1] = __uint_as_float(bits & ~63u);
    }
    __syncwarp();

    // ---- dists: pos = j + prefix[j] ----
    obf[lane + pref[lane]]           = dA;
    obf[lane + 32 + pref[lane + 32]] = dB;
    __syncwarp();

    // ---- coalesced output ----
    float* optr = out + (size_t)ray * NOUT;
    #pragma unroll
    for (int t = 0; t < 6; t++)
        optr[t * 32 + lane] = obf[t * 32 + lane];
}

extern "C" void kernel_launch(void* const* d_in, const int* in_sizes, int n_in,
                              void* d_out, int out_size) {
    const float* dists   = (const float*)d_in[0];
    const float* weights = (const float*)d_in[1];
    const float* rands   = (const float*)d_in[2];
    float* out = (float*)d_out;
    int B = in_sizes[0] / SC;
    int blocks = (B + WPB - 1) / WPB;
    fine_sample_kernel<<<blocks, 32 * WPB>>>(dists, weights, rands, out, B);
}

// round 4
// speedup vs baseline: 1.1752x; 1.1752x over previous
#include <cuda_runtime.h>

// NeRF fine sampling + merge. One warp per ray.
// SC=64 sorted coarse dists, 63 weights, SF=128 fine samples, out 192 sorted.
#define SC   64
#define SF   128
#define NOUT 192
#define WPB  8
#define FULL 0xffffffffu

__device__ __forceinline__ void ce(float& x, float& y, bool asc) {
    float lo = fminf(x, y), hi = fmaxf(x, y);
    x = asc ? lo : hi;
    y = asc ? hi : lo;
}

__global__ __launch_bounds__(32 * WPB, 6)
void fine_sample_kernel(const float* __restrict__ dists,
                        const float* __restrict__ weights,
                        const float* __restrict__ rands,
                        float* __restrict__ out, int B)
{
    __shared__ float2 pair_s[WPB][SC];   // (cdf[i], dist[i])
    __shared__ float  cdfs_s[WPB][SC];   // scalar cdf for search probes
    __shared__ int    pref_s[WPB][SC];   // first-rank-per-bin table
    __shared__ float  out_s[WPB][NOUT];

    const int wid  = threadIdx.x >> 5;
    const int lane = threadIdx.x & 31;
    const int ray  = blockIdx.x * WPB + wid;
    if (ray >= B) return;

    float2* pair = pair_s[wid];
    float*  cdfs = cdfs_s[wid];
    int*    pref = pref_s[wid];
    float*  obf  = out_s[wid];

    // default: "no sample has bin >= j" -> 128
    pref[lane]      = 128;
    pref[lane + 32] = 128;

    // ---- load coarse dists ----
    const float* dptr = dists + (size_t)ray * SC;
    float dA = dptr[lane];
    float dB = dptr[32 + lane];

    // ---- weights -> normalized CDF ----
    const float* wptr = weights + (size_t)ray * (SC - 1);
    float w0 = wptr[lane] + 0.01f;
    float w1 = (lane < 31) ? (wptr[32 + lane] + 0.01f) : 0.0f;

    float a = w0;
    #pragma unroll
    for (int off = 1; off < 32; off <<= 1) {
        float t = __shfl_up_sync(FULL, a, off);
        if (lane >= off) a += t;
    }
    float total0 = __shfl_sync(FULL, a, 31);
    float b = w1;
    #pragma unroll
    for (int off = 1; off < 32; off <<= 1) {
        float t = __shfl_up_sync(FULL, b, off);
        if (lane >= off) b += t;
    }
    float total = total0 + __shfl_sync(FULL, b, 30);
    float inv = 1.0f / total;

    float v1 = a * inv;              // cdf[lane+1]
    float v2 = (total0 + b) * inv;   // cdf[lane+33]

    if (lane == 0) cdfs[0] = 0.0f;
    cdfs[lane + 1] = v1;
    if (lane < 31) cdfs[lane + 33] = v2;

    float c32v = __shfl_sync(FULL, v1, 31);
    float cl = __shfl_up_sync(FULL, v1, 1); if (lane == 0) cl = 0.0f;
    float ch = __shfl_up_sync(FULL, v2, 1); if (lane == 0) ch = c32v;
    pair[lane]      = make_float2(cl, dA);
    pair[lane + 32] = make_float2(ch, dB);

    // register-resident top search levels
    float c16 = __shfl_sync(FULL, v1, 15);
    float c8  = __shfl_sync(FULL, v1, 7);
    float c24 = __shfl_sync(FULL, v1, 23);
    float c48 = __shfl_sync(FULL, v2, 15);
    float c40 = __shfl_sync(FULL, v2, 7);
    float c56 = __shfl_sync(FULL, v2, 23);
    __syncwarp();

    // ---- 4 samples per lane, element index i = lane*4 + m ----
    const float4* u4p = (const float4*)(rands + (size_t)ray * SF);
    float4 uu = u4p[lane];
    float uarr[4] = {uu.x, uu.y, uu.z, uu.w};
    float k[4];

    #pragma unroll
    for (int m = 0; m < 4; m++) {
        float u = uarr[m];
        int idx = (c32v <= u) ? 32 : 0;
        float p2 = idx ? c48 : c16;
        if (p2 <= u) idx += 16;
        float p3 = (idx & 32) ? ((idx & 16) ? c56 : c40)
                              : ((idx & 16) ? c24 : c8);
        if (p3 <= u) idx += 8;
        if (cdfs[idx + 4] <= u) idx += 4;
        if (cdfs[idx + 2] <= u) idx += 2;
        if (cdfs[idx + 1] <= u) idx += 1;
        int above = min(SC - 1, idx + 1);
        float2 p0 = pair[idx];
        float2 p1 = pair[above];
        float den = p1.x - p0.x;
        den = (den < 1e-5f) ? 1.0f : den;
        float t = (u - p0.x) / den;
        float s = fmaf(t, p1.y - p0.y, p0.y);
        s = fminf(s, p1.y);   // bin-monotone keys
        k[m] = __uint_as_float((__float_as_uint(s) & ~63u) | (unsigned)idx);
    }

    // ---- bitonic sort of 128 keys, blocked mapping i = lane*4+m ----
    ce(k[0], k[1], true);  ce(k[2], k[3], false);       // k=2
    {                                                    // k=4
        bool a4 = (lane & 1) == 0;
        ce(k[0], k[2], a4); ce(k[1], k[3], a4);
        ce(k[0], k[1], a4); ce(k[2], k[3], a4);
    }
    #pragma unroll
    for (int kk = 8; kk <= SF; kk <<= 1) {
        bool asc = (lane & (kk >> 2)) == 0;
        #pragma unroll
        for (int j = kk >> 1; j >= 4; j >>= 1) {
            int L = j >> 2;                  // lane distance
            bool domin = (((lane & L) == 0) == asc);
            #pragma unroll
            for (int m = 0; m < 4; m++) {
                float p = __shfl_xor_sync(FULL, k[m], L);
                k[m] = domin ? fminf(k[m], p) : fmaxf(k[m], p);
            }
        }
        ce(k[0], k[2], asc); ce(k[1], k[3], asc);
        ce(k[0], k[1], asc); ce(k[2], k[3], asc);
    }

    // ---- branchless first-occurrence writes: pref[bin] = first rank ----
    int bb[4];
    #pragma unroll
    for (int m = 0; m < 4; m++) bb[m] = (int)(__float_as_uint(k[m]) & 63u);
    int pb = __shfl_up_sync(FULL, bb[3], 1);
    if (lane == 0) pb = -1;
    if (bb[0] != pb)    pref[bb[0]] = lane * 4;
    if (bb[1] != bb[0]) pref[bb[1]] = lane * 4 + 1;
    if (bb[2] != bb[1]) pref[bb[2]] = lane * 4 + 2;
    if (bb[3] != bb[2]) pref[bb[3]] = lane * 4 + 3;

    // ---- scatter samples: pos = rank + bin + 1 ----
    #pragma unroll
    for (int m = 0; m < 4; m++) {
        unsigned bits = __float_as_uint(k[m]);
        obf[lane * 4 + m + bb[m] + 1] = __uint_as_float(bits & ~63u);
    }
    __syncwarp();

    // ---- suffix-min over pref[0..63] in registers ----
    int A = pref[lane];
    int Bv = pref[lane + 32];
    #pragma unroll
    for (int off = 1; off < 32; off <<= 1) {
        int tA = __shfl_down_sync(FULL, A, off);
        int tB = __shfl_down_sync(FULL, Bv, off);
        if (lane + off < 32) { A = min(A, tA); Bv = min(Bv, tB); }
    }
    int bAll = __shfl_sync(FULL, Bv, 0);
    A = min(A, bAll);

    // ---- dists: pos = j + prefix[j] ----
    obf[lane + A]        = dA;
    obf[lane + 32 + Bv]  = dB;
    __syncwarp();

    // ---- coalesced output ----
    float* optr = out + (size_t)ray * NOUT;
    #pragma unroll
    for (int t = 0; t < 6; t++)
        optr[t * 32 + lane] = obf[t * 32 + lane];
}

extern "C" void kernel_launch(void* const* d_in, const int* in_sizes, int n_in,
                              void* d_out, int out_size) {
    const float* dists   = (const float*)d_in[0];
    const float* weights = (const float*)d_in[1];
    const float* rands   = (const float*)d_in[2];
    float* out = (float*)d_out;
    int B = in_sizes[0] / SC;
    int blocks = (B + WPB - 1) / WPB;
    fine_sample_kernel<<<blocks, 32 * WPB>>>(dists, weights, rands, out, B);
}

// round 5
// speedup vs baseline: 1.2268x; 1.0439x over previous
#include <cuda_runtime.h>

// NeRF fine sampling + merge. One warp per ray.
// SC=64 sorted coarse dists, 63 weights, SF=128 fine samples, out 192 sorted.
#define SC   64
#define SF   128
#define NOUT 192
#define WPB  8
#define FULL 0xffffffffu

__device__ __forceinline__ void ce(float& x, float& y, bool asc) {
    float lo = fminf(x, y), hi = fmaxf(x, y);
    x = asc ? lo : hi;
    y = asc ? hi : lo;
}

__global__ __launch_bounds__(32 * WPB, 6)
void fine_sample_kernel(const float* __restrict__ dists,
                        const float* __restrict__ weights,
                        const float* __restrict__ rands,
                        float* __restrict__ out, int B)
{
    __shared__ float cdfs_s[WPB][SC + 2];  // cdf[0..64] (+pad)
    __shared__ float dst_s[WPB][SC + 2];   // d[0..64] (+pad)
    __shared__ int   pref_s[WPB][SC];      // first-rank-per-bin table
    __shared__ float out_s[WPB][NOUT];

    const int wid  = threadIdx.x >> 5;
    const int lane = threadIdx.x & 31;
    const int ray  = blockIdx.x * WPB + wid;
    if (ray >= B) return;

    float* cdfs = cdfs_s[wid];
    float* dst  = dst_s[wid];
    int*   pref = pref_s[wid];
    float* obf  = out_s[wid];

    // default: "no sample has bin >= j" -> 128
    pref[lane]      = 128;
    pref[lane + 32] = 128;

    // ---- load coarse dists ----
    const float* dptr = dists + (size_t)ray * SC;
    float dA = dptr[lane];
    float dB = dptr[32 + lane];
    dst[lane]      = dA;
    dst[32 + lane] = dB;
    if (lane == 31) dst[64] = dB;          // sentinel d[64] = d[63]

    // ---- weights -> normalized CDF via single pair-scan ----
    const float* wptr = weights + (size_t)ray * (SC - 1);
    float wa, wb;
    if (lane < 31) { wa = wptr[2 * lane] + 0.01f; wb = wptr[2 * lane + 1] + 0.01f; }
    else           { wa = wptr[62] + 0.01f;        wb = 0.0f; }
    float e = wa + wb;
    float E = e;
    #pragma unroll
    for (int off = 1; off < 32; off <<= 1) {
        float t = __shfl_up_sync(FULL, E, off);
        if (lane >= off) E += t;
    }
    float total = __shfl_sync(FULL, E, 31);
    float inv = 1.0f / total;

    // cdf[2l+1] = (E - wb)*inv ; cdf[2l+2] = E*inv  -> fills cdf[1..64] (64 = sentinel 1.0)
    cdfs[2 * lane + 1] = (E - wb) * inv;
    cdfs[2 * lane + 2] = E * inv;
    if (lane == 0) cdfs[0] = 0.0f;

    // register-resident top 3 search levels (all even cdf indices = E_l * inv)
    float c32v = __shfl_sync(FULL, E, 15) * inv;
    float c16  = __shfl_sync(FULL, E, 7)  * inv;
    float c48  = __shfl_sync(FULL, E, 23) * inv;
    float c8   = __shfl_sync(FULL, E, 3)  * inv;
    float c24  = __shfl_sync(FULL, E, 11) * inv;
    float c40  = __shfl_sync(FULL, E, 19) * inv;
    float c56  = __shfl_sync(FULL, E, 27) * inv;

    // ---- load 4 u's per lane (blocked: element i = lane*4 + m) ----
    const float4* u4p = (const float4*)(rands + (size_t)ray * SF);
    float4 uu = u4p[lane];
    float k[4] = {uu.x, uu.y, uu.z, uu.w};

    // ---- bitonic sort of the 128 u's (all positive floats) ----
    ce(k[0], k[1], true);  ce(k[2], k[3], false);       // k=2
    {                                                    // k=4
        bool a4 = (lane & 1) == 0;
        ce(k[0], k[2], a4); ce(k[1], k[3], a4);
        ce(k[0], k[1], a4); ce(k[2], k[3], a4);
    }
    #pragma unroll
    for (int kk = 8; kk <= SF; kk <<= 1) {
        bool asc = (lane & (kk >> 2)) == 0;
        #pragma unroll
        for (int j = kk >> 1; j >= 4; j >>= 1) {
            int L = j >> 2;
            bool domin = (((lane & L) == 0) == asc);
            #pragma unroll
            for (int m = 0; m < 4; m++) {
                float p = __shfl_xor_sync(FULL, k[m], L);
                k[m] = domin ? fminf(k[m], p) : fmaxf(k[m], p);
            }
        }
        ce(k[0], k[2], asc); ce(k[1], k[3], asc);
        ce(k[0], k[1], asc); ce(k[2], k[3], asc);
    }
    __syncwarp();   // cdf/dst tables ready; sort covered the latency

    // ---- search + interp on SORTED u's (monotone indices -> low-conflict LDS) ----
    int bb[4];
    #pragma unroll
    for (int m = 0; m < 4; m++) {
        float u = k[m];
        int idx = (c32v <= u) ? 32 : 0;
        float p2 = idx ? c48 : c16;
        if (p2 <= u) idx += 16;
        float p3 = (idx & 32) ? ((idx & 16) ? c56 : c40)
                              : ((idx & 16) ? c24 : c8);
        if (p3 <= u) idx += 8;
        if (cdfs[idx + 4] <= u) idx += 4;
        if (cdfs[idx + 2] <= u) idx += 2;
        if (cdfs[idx + 1] <= u) idx += 1;
        bb[m] = idx;
        float c0 = cdfs[idx], c1 = cdfs[idx + 1];
        float d0 = dst[idx],  d1 = dst[idx + 1];
        float den = c1 - c0;
        den = (den < 1e-5f) ? 1.0f : den;
        float t = (u - c0) / den;
        float s = fmaf(t, d1 - d0, d0);
        s = fminf(s, d1);                       // fp guard: keep s within bin
        // sample position: rank + bin + 1
        obf[lane * 4 + m + idx + 1] = s;
    }

    // ---- branchless first-occurrence writes: pref[bin] = first rank ----
    int pb = __shfl_up_sync(FULL, bb[3], 1);
    if (lane == 0) pb = -1;
    if (bb[0] != pb)    pref[bb[0]] = lane * 4;
    if (bb[1] != bb[0]) pref[bb[1]] = lane * 4 + 1;
    if (bb[2] != bb[1]) pref[bb[2]] = lane * 4 + 2;
    if (bb[3] != bb[2]) pref[bb[3]] = lane * 4 + 3;
    __syncwarp();

    // ---- suffix-min over pref[0..63] in registers ----
    int A  = pref[lane];
    int Bv = pref[lane + 32];
    #pragma unroll
    for (int off = 1; off < 32; off <<= 1) {
        int tA = __shfl_down_sync(FULL, A, off);
        int tB = __shfl_down_sync(FULL, Bv, off);
        if (lane + off < 32) { A = min(A, tA); Bv = min(Bv, tB); }
    }
    int bAll = __shfl_sync(FULL, Bv, 0);
    A = min(A, bAll);

    // ---- dists: pos = j + prefix[j] ----
    obf[lane + A]       = dA;
    obf[lane + 32 + Bv] = dB;
    __syncwarp();

    // ---- coalesced output ----
    float* optr = out + (size_t)ray * NOUT;
    #pragma unroll
    for (int t = 0; t < 6; t++)
        optr[t * 32 + lane] = obf[t * 32 + lane];
}

extern "C" void kernel_launch(void* const* d_in, const int* in_sizes, int n_in,
                              void* d_out, int out_size) {
    const float* dists   = (const float*)d_in[0];
    const float* weights = (const float*)d_in[1];
    const float* rands   = (const float*)d_in[2];
    float* out = (float*)d_out;
    int B = in_sizes[0] / SC;
    int blocks = (B + WPB - 1) / WPB;
    fine_sample_kernel<<<blocks, 32 * WPB>>>(dists, weights, rands, out, B);
}